// round 2
// baseline (speedup 1.0000x reference)
#include <cuda_runtime.h>
#include <math.h>

#define BATCH 1024
#define INPUT_SIZE 512
#define HIDDEN 1024
#define N_QP 64
#define M_QP 128
#define QP_ITER 50
#define N_P 2080          // 64*65/2
#define N_HMAT 8192       // 128*64
#define N_OUT 10464       // 2080 + 64 + 8192 + 128
#define HOFF 2144         // N_P + N_QP

// Intermediate buffers (no allocations allowed); 16B aligned for float4 access
__device__ __align__(16) float g_h1[BATCH * HIDDEN];
__device__ __align__(16) float g_h2[BATCH * HIDDEN];
__device__ __align__(16) float g_out3[BATCH * N_OUT];

// ---------------------------------------------------------------------------
// Tiled fp32 SGEMM with fused bias (+ optional ReLU).  (unchanged, at fp32 peak)
// ---------------------------------------------------------------------------
template <bool RELU>
__global__ __launch_bounds__(256)
void sgemm_bias(const float* __restrict__ A, const float* __restrict__ B,
                const float* __restrict__ bias, float* __restrict__ C,
                int M, int N, int K)
{
    __shared__ float As[16 * 65];   // transposed: As[k][m], pad 65
    __shared__ float Bs[16 * 64];   // Bs[k][n]

    const int tid = threadIdx.x;
    const int tx = tid & 15;
    const int ty = tid >> 4;
    const int m0 = blockIdx.y * 64;
    const int n0 = blockIdx.x * 64;

    const int aRow = tid >> 2;
    const int aC4  = tid & 3;
    const int bRow = tid >> 4;
    const int bC4  = tid & 15;

    float acc[4][4] = {};

    for (int k0 = 0; k0 < K; k0 += 16) {
        float4 av = *(const float4*)&A[(size_t)(m0 + aRow) * K + k0 + aC4 * 4];
        int bn = n0 + bC4 * 4;
        float4 bv = make_float4(0.f, 0.f, 0.f, 0.f);
        if (bn < N) bv = *(const float4*)&B[(size_t)(k0 + bRow) * N + bn];

        __syncthreads();
        As[(aC4 * 4 + 0) * 65 + aRow] = av.x;
        As[(aC4 * 4 + 1) * 65 + aRow] = av.y;
        As[(aC4 * 4 + 2) * 65 + aRow] = av.z;
        As[(aC4 * 4 + 3) * 65 + aRow] = av.w;
        *(float4*)&Bs[bRow * 64 + bC4 * 4] = bv;
        __syncthreads();

        #pragma unroll
        for (int k = 0; k < 16; ++k) {
            float4 bb = *(const float4*)&Bs[k * 64 + tx * 4];
            float a0 = As[k * 65 + ty * 4 + 0];
            float a1 = As[k * 65 + ty * 4 + 1];
            float a2 = As[k * 65 + ty * 4 + 2];
            float a3 = As[k * 65 + ty * 4 + 3];
            acc[0][0] = fmaf(a0, bb.x, acc[0][0]);
            acc[0][1] = fmaf(a0, bb.y, acc[0][1]);
            acc[0][2] = fmaf(a0, bb.z, acc[0][2]);
            acc[0][3] = fmaf(a0, bb.w, acc[0][3]);
            acc[1][0] = fmaf(a1, bb.x, acc[1][0]);
            acc[1][1] = fmaf(a1, bb.y, acc[1][1]);
            acc[1][2] = fmaf(a1, bb.z, acc[1][2]);
            acc[1][3] = fmaf(a1, bb.w, acc[1][3]);
            acc[2][0] = fmaf(a2, bb.x, acc[2][0]);
            acc[2][1] = fmaf(a2, bb.y, acc[2][1]);
            acc[2][2] = fmaf(a2, bb.z, acc[2][2]);
            acc[2][3] = fmaf(a2, bb.w, acc[2][3]);
            acc[3][0] = fmaf(a3, bb.x, acc[3][0]);
            acc[3][1] = fmaf(a3, bb.y, acc[3][1]);
            acc[3][2] = fmaf(a3, bb.z, acc[3][2]);
            acc[3][3] = fmaf(a3, bb.w, acc[3][3]);
        }
    }

    #pragma unroll
    for (int ii = 0; ii < 4; ++ii) {
        int m = m0 + ty * 4 + ii;
        #pragma unroll
        for (int jj = 0; jj < 4; ++jj) {
            int n = n0 + tx * 4 + jj;
            if (n < N) {
                float v = acc[ii][jj] + bias[n];
                if (RELU) v = fmaxf(v, 0.f);
                C[(size_t)m * N + n] = v;
            }
        }
    }
}

// ---------------------------------------------------------------------------
// Register-resident per-batch QP solver. One CTA (256 thr) per batch item.
//
// Thread-register layout:
//   rH [32]: thread t holds H[r][32h+k],  r = t>>1, h = t&1      (row slices)
//   rHT[32]: thread t holds H[32g+j][c],  c = t>>2, g = t&3      (col slices)
//   rM [16]: thread t holds Minv[i][16s+j], i = t>>2, s = t&3
// Vector operands live in smem, read as float4 broadcasts.
// ---------------------------------------------------------------------------
__device__ __forceinline__ float sel16(const float* r, int kj) {
    float v = r[0];
    #pragma unroll
    for (int j = 1; j < 16; ++j) v = (j == kj) ? r[j] : v;
    return v;
}

__global__ __launch_bounds__(256, 2)
void solver_kernel(const float* __restrict__ out3, float* __restrict__ xs)
{
    __shared__ __align__(16) float sL[64 * 65];
    __shared__ __align__(16) float sP[64 * 65];
    __shared__ __align__(16) float sxbar[64];
    __shared__ __align__(16) float st[64];
    __shared__ __align__(16) float slam[128];
    __shared__ __align__(16) float sb[128];
    __shared__ __align__(16) float sq[64];
    __shared__ __align__(16) float sv[64];
    __shared__ __align__(16) float sw[128];
    __shared__ __align__(16) float spiv[64];
    __shared__ __align__(16) float sfac[64];
    __shared__ float spart[8];
    __shared__ float s_scal, s_tau, s_piv;

    const int t    = threadIdx.x;
    const int lane = t & 31;
    const int warp = t >> 5;
    const int r    = t >> 1;   // rH row
    const int h    = t & 1;    // rH half
    const int c    = t >> 2;   // rHT col == rM row
    const int g    = t & 3;    // rHT quarter == rM segment

    const float* row = out3 + (size_t)blockIdx.x * N_OUT;

    // ---- Load H row & column slices into registers ----
    float rH[32], rHT[32];
    {
        const float4* base = (const float4*)(row + HOFF + r * 64 + 32 * h);
        #pragma unroll
        for (int k4 = 0; k4 < 8; ++k4) {
            float4 v = base[k4];
            rH[4*k4+0] = v.x; rH[4*k4+1] = v.y; rH[4*k4+2] = v.z; rH[4*k4+3] = v.w;
        }
        #pragma unroll
        for (int j = 0; j < 32; ++j)
            rHT[j] = row[HOFF + (32 * g + j) * 64 + c];
    }
    // q, b
    if (t < 64)  sq[t] = row[N_P + t];
    if (t < 128) sb[t] = row[HOFF + N_HMAT + t];
    if (t < 64)  sv[t] = 0.125f;   // 1/sqrt(64)
    __syncthreads();

    // ================= Power iteration (register matvecs) =================
    for (int pit = 0; pit < 10; ++pit) {
        // w = H v
        {
            const float4* x4 = (const float4*)(sv + 32 * h);
            float s = 0.f;
            #pragma unroll
            for (int k4 = 0; k4 < 8; ++k4) {
                float4 xv = x4[k4];
                s = fmaf(rH[4*k4+0], xv.x, s);
                s = fmaf(rH[4*k4+1], xv.y, s);
                s = fmaf(rH[4*k4+2], xv.z, s);
                s = fmaf(rH[4*k4+3], xv.w, s);
            }
            s += __shfl_xor_sync(0xffffffffu, s, 1);
            if (h == 0) sw[r] = s;
        }
        __syncthreads();
        // tvec = H^T w ; norm
        {
            const float4* w4 = (const float4*)(sw + 32 * g);
            float p = 0.f;
            #pragma unroll
            for (int j4 = 0; j4 < 8; ++j4) {
                float4 wv = w4[j4];
                p = fmaf(rHT[4*j4+0], wv.x, p);
                p = fmaf(rHT[4*j4+1], wv.y, p);
                p = fmaf(rHT[4*j4+2], wv.z, p);
                p = fmaf(rHT[4*j4+3], wv.w, p);
            }
            p += __shfl_xor_sync(0xffffffffu, p, 1);
            p += __shfl_xor_sync(0xffffffffu, p, 2);
            float pp = (g == 0) ? p * p : 0.f;
            #pragma unroll
            for (int off = 16; off >= 1; off >>= 1)
                pp += __shfl_xor_sync(0xffffffffu, pp, off);
            if (lane == 0) spart[warp] = pp;
            __syncthreads();
            if (t == 0) {
                float sm = 0.f;
                #pragma unroll
                for (int i = 0; i < 8; ++i) sm += spart[i];
                s_scal = sqrtf(sm) + 1e-12f;
            }
            __syncthreads();
            if (g == 0) sv[c] = p / s_scal;
        }
        __syncthreads();
    }

    // ---- sn = ||H v|| + 1e-6 ; tau = 0.9/sn ----
    {
        const float4* x4 = (const float4*)(sv + 32 * h);
        float s = 0.f;
        #pragma unroll
        for (int k4 = 0; k4 < 8; ++k4) {
            float4 xv = x4[k4];
            s = fmaf(rH[4*k4+0], xv.x, s);
            s = fmaf(rH[4*k4+1], xv.y, s);
            s = fmaf(rH[4*k4+2], xv.z, s);
            s = fmaf(rH[4*k4+3], xv.w, s);
        }
        s += __shfl_xor_sync(0xffffffffu, s, 1);
        float pp = (h == 0) ? s * s : 0.f;
        #pragma unroll
        for (int off = 16; off >= 1; off >>= 1)
            pp += __shfl_xor_sync(0xffffffffu, pp, off);
        if (lane == 0) spart[warp] = pp;
        __syncthreads();
        if (t == 0) {
            float sm = 0.f;
            #pragma unroll
            for (int i = 0; i < 8; ++i) sm += spart[i];
            s_tau = 0.9f / (sqrtf(sm) + 1e-6f);
        }
    }

    // ================= Build L (scatter + softplus diagonal) =================
    for (int idx = t; idx < 64 * 65; idx += 256) sL[idx] = 0.f;
    __syncthreads();
    for (int idx = t; idx < N_P; idx += 256) {
        float p = row[idx];
        int rr = (int)((sqrtf(8.f * (float)idx + 1.f) - 1.f) * 0.5f);
        while ((rr * (rr + 1)) / 2 > idx) --rr;
        while (((rr + 1) * (rr + 2)) / 2 <= idx) ++rr;
        int cc = idx - (rr * (rr + 1)) / 2;
        float val;
        if (cc == rr) {
            float sp = fmaxf(p, 0.f) + log1pf(expf(-fabsf(p)));  // softplus
            val = 0.1f + sp;
        } else {
            val = p;
        }
        sL[rr * 65 + cc] = val;
    }
    __syncthreads();
    const float tau = s_tau;
    const float sig = tau;

    // ================= P = L L^T  (4x4 register blocking) =================
    {
        const int tm = t >> 4, tn = t & 15;
        const int i0 = 4 * tm, j0 = 4 * tn;
        float acc[4][4] = {};
        #pragma unroll 4
        for (int k = 0; k < 64; ++k) {
            float a0 = sL[(i0+0)*65 + k], a1 = sL[(i0+1)*65 + k];
            float a2 = sL[(i0+2)*65 + k], a3 = sL[(i0+3)*65 + k];
            float b0 = sL[(j0+0)*65 + k], b1 = sL[(j0+1)*65 + k];
            float b2 = sL[(j0+2)*65 + k], b3 = sL[(j0+3)*65 + k];
            acc[0][0]=fmaf(a0,b0,acc[0][0]); acc[0][1]=fmaf(a0,b1,acc[0][1]);
            acc[0][2]=fmaf(a0,b2,acc[0][2]); acc[0][3]=fmaf(a0,b3,acc[0][3]);
            acc[1][0]=fmaf(a1,b0,acc[1][0]); acc[1][1]=fmaf(a1,b1,acc[1][1]);
            acc[1][2]=fmaf(a1,b2,acc[1][2]); acc[1][3]=fmaf(a1,b3,acc[1][3]);
            acc[2][0]=fmaf(a2,b0,acc[2][0]); acc[2][1]=fmaf(a2,b1,acc[2][1]);
            acc[2][2]=fmaf(a2,b2,acc[2][2]); acc[2][3]=fmaf(a2,b3,acc[2][3]);
            acc[3][0]=fmaf(a3,b0,acc[3][0]); acc[3][1]=fmaf(a3,b1,acc[3][1]);
            acc[3][2]=fmaf(a3,b2,acc[3][2]); acc[3][3]=fmaf(a3,b3,acc[3][3]);
        }
        #pragma unroll
        for (int a = 0; a < 4; ++a)
            #pragma unroll
            for (int b = 0; b < 4; ++b)
                sP[(i0+a)*65 + j0 + b] = acc[a][b];
    }
    __syncthreads();

    // ================= rM = I + tau * P  (registers), then Gauss-Jordan ====
    float rM[16];
    #pragma unroll
    for (int j = 0; j < 16; ++j) {
        int col = 16 * g + j;
        float m = tau * sP[c * 65 + col];
        rM[j] = (col == c) ? (m + 1.f) : m;
    }
    __syncthreads();

    for (int k = 0; k < 64; ++k) {
        const int kc = k >> 4, kj = k & 15;
        if (c == k && g == kc) s_piv = sel16(rM, kj);
        __syncthreads();
        const float piv = 1.f / s_piv;
        if (g == kc) sfac[c] = sel16(rM, kj);   // old column-k value (factor)
        if (c == k) {
            #pragma unroll
            for (int j = 0; j < 16; ++j) {
                bool isk = (g == kc) && (j == kj);
                rM[j] = isk ? piv : rM[j] * piv;
                spiv[16 * g + j] = rM[j];
            }
        }
        __syncthreads();
        if (c != k) {
            const float f = sfac[c];
            #pragma unroll
            for (int j = 0; j < 16; ++j) {
                bool isk = (g == kc) && (j == kj);
                float upd = fmaf(-f, spiv[16 * g + j], rM[j]);
                rM[j] = isk ? (-f * piv) : upd;
            }
        }
        __syncthreads();
    }

    // ================= QP iterations =================
    if (t < 64)  { sxbar[t] = 0.f; st[t] = 0.f; }
    if (t < 128) slam[t] = 0.f;
    float xp = 0.f;   // x-prev, owned by group leaders (g==0), index c
    __syncthreads();

    for (int it = 0; it < QP_ITER; ++it) {
        // lam = relu(lam - sig*(H xbar + b))
        {
            const float4* x4 = (const float4*)(sxbar + 32 * h);
            float s = 0.f;
            #pragma unroll
            for (int k4 = 0; k4 < 8; ++k4) {
                float4 xv = x4[k4];
                s = fmaf(rH[4*k4+0], xv.x, s);
                s = fmaf(rH[4*k4+1], xv.y, s);
                s = fmaf(rH[4*k4+2], xv.z, s);
                s = fmaf(rH[4*k4+3], xv.w, s);
            }
            s += __shfl_xor_sync(0xffffffffu, s, 1);
            if (h == 0) slam[r] = fmaxf(0.f, slam[r] - sig * (s + sb[r]));
        }
        __syncthreads();
        // tvec = xp + tau*(H^T lam - q)
        {
            const float4* l4 = (const float4*)(slam + 32 * g);
            float p = 0.f;
            #pragma unroll
            for (int j4 = 0; j4 < 8; ++j4) {
                float4 lv = l4[j4];
                p = fmaf(rHT[4*j4+0], lv.x, p);
                p = fmaf(rHT[4*j4+1], lv.y, p);
                p = fmaf(rHT[4*j4+2], lv.z, p);
                p = fmaf(rHT[4*j4+3], lv.w, p);
            }
            p += __shfl_xor_sync(0xffffffffu, p, 1);
            p += __shfl_xor_sync(0xffffffffu, p, 2);
            if (g == 0) st[c] = xp + tau * (p - sq[c]);
        }
        __syncthreads();
        // xn = Minv tvec ; xbar = 2 xn - xp ; xp = xn
        {
            const float4* t4 = (const float4*)(st + 16 * g);
            float p = 0.f;
            #pragma unroll
            for (int j4 = 0; j4 < 4; ++j4) {
                float4 tv = t4[j4];
                p = fmaf(rM[4*j4+0], tv.x, p);
                p = fmaf(rM[4*j4+1], tv.y, p);
                p = fmaf(rM[4*j4+2], tv.z, p);
                p = fmaf(rM[4*j4+3], tv.w, p);
            }
            p += __shfl_xor_sync(0xffffffffu, p, 1);
            p += __shfl_xor_sync(0xffffffffu, p, 2);
            if (g == 0) {
                sxbar[c] = 2.f * p - xp;
                xp = p;
            }
        }
        __syncthreads();
    }

    if (g == 0) xs[(size_t)blockIdx.x * N_QP + c] = xp;
}

// ---------------------------------------------------------------------------
// Launch
// ---------------------------------------------------------------------------
extern "C" void kernel_launch(void* const* d_in, const int* in_sizes, int n_in,
                              void* d_out, int out_size)
{
    const float* x  = (const float*)d_in[0];
    const float* W1 = (const float*)d_in[1];
    const float* b1 = (const float*)d_in[2];
    const float* W2 = (const float*)d_in[3];
    const float* b2 = (const float*)d_in[4];
    const float* W3 = (const float*)d_in[5];
    const float* b3 = (const float*)d_in[6];
    float* out = (float*)d_out;

    float *p_h1, *p_h2, *p_out3;
    cudaGetSymbolAddress((void**)&p_h1, g_h1);
    cudaGetSymbolAddress((void**)&p_h2, g_h2);
    cudaGetSymbolAddress((void**)&p_out3, g_out3);

    {
        dim3 grid(HIDDEN / 64, BATCH / 64);
        sgemm_bias<true><<<grid, 256>>>(x, W1, b1, p_h1, BATCH, HIDDEN, INPUT_SIZE);
    }
    {
        dim3 grid(HIDDEN / 64, BATCH / 64);
        sgemm_bias<true><<<grid, 256>>>(p_h1, W2, b2, p_h2, BATCH, HIDDEN, HIDDEN);
    }
    {
        dim3 grid((N_OUT + 63) / 64, BATCH / 64);
        sgemm_bias<false><<<grid, 256>>>(p_h2, W3, b3, p_out3, BATCH, N_OUT, HIDDEN);
    }
    solver_kernel<<<BATCH, 256>>>(p_out3, out);
}

// round 4
// speedup vs baseline: 1.0839x; 1.0839x over previous
#include <cuda_runtime.h>
#include <math.h>

#define BATCH 1024
#define INPUT_SIZE 512
#define HIDDEN 1024
#define N_QP 64
#define M_QP 128
#define QP_ITER 50
#define N_P 2080          // 64*65/2
#define N_HMAT 8192       // 128*64
#define N_OUT 10464       // 2080 + 64 + 8192 + 128
#define HOFF 2144         // N_P + N_QP

__device__ __align__(16) float g_h1[BATCH * HIDDEN];
__device__ __align__(16) float g_h2[BATCH * HIDDEN];
__device__ __align__(16) float g_out3[BATCH * N_OUT];

// ---------------------------------------------------------------------------
// Tiled fp32 SGEMM with fused bias (+ optional ReLU) — unchanged (at fp32 peak)
// ---------------------------------------------------------------------------
template <bool RELU>
__global__ __launch_bounds__(256)
void sgemm_bias(const float* __restrict__ A, const float* __restrict__ B,
                const float* __restrict__ bias, float* __restrict__ C,
                int M, int N, int K)
{
    __shared__ float As[16 * 65];
    __shared__ float Bs[16 * 64];

    const int tid = threadIdx.x;
    const int tx = tid & 15;
    const int ty = tid >> 4;
    const int m0 = blockIdx.y * 64;
    const int n0 = blockIdx.x * 64;

    const int aRow = tid >> 2;
    const int aC4  = tid & 3;
    const int bRow = tid >> 4;
    const int bC4  = tid & 15;

    float acc[4][4] = {};

    for (int k0 = 0; k0 < K; k0 += 16) {
        float4 av = *(const float4*)&A[(size_t)(m0 + aRow) * K + k0 + aC4 * 4];
        int bn = n0 + bC4 * 4;
        float4 bv = make_float4(0.f, 0.f, 0.f, 0.f);
        if (bn < N) bv = *(const float4*)&B[(size_t)(k0 + bRow) * N + bn];

        __syncthreads();
        As[(aC4 * 4 + 0) * 65 + aRow] = av.x;
        As[(aC4 * 4 + 1) * 65 + aRow] = av.y;
        As[(aC4 * 4 + 2) * 65 + aRow] = av.z;
        As[(aC4 * 4 + 3) * 65 + aRow] = av.w;
        *(float4*)&Bs[bRow * 64 + bC4 * 4] = bv;
        __syncthreads();

        #pragma unroll
        for (int k = 0; k < 16; ++k) {
            float4 bb = *(const float4*)&Bs[k * 64 + tx * 4];
            float a0 = As[k * 65 + ty * 4 + 0];
            float a1 = As[k * 65 + ty * 4 + 1];
            float a2 = As[k * 65 + ty * 4 + 2];
            float a3 = As[k * 65 + ty * 4 + 3];
            acc[0][0] = fmaf(a0, bb.x, acc[0][0]);
            acc[0][1] = fmaf(a0, bb.y, acc[0][1]);
            acc[0][2] = fmaf(a0, bb.z, acc[0][2]);
            acc[0][3] = fmaf(a0, bb.w, acc[0][3]);
            acc[1][0] = fmaf(a1, bb.x, acc[1][0]);
            acc[1][1] = fmaf(a1, bb.y, acc[1][1]);
            acc[1][2] = fmaf(a1, bb.z, acc[1][2]);
            acc[1][3] = fmaf(a1, bb.w, acc[1][3]);
            acc[2][0] = fmaf(a2, bb.x, acc[2][0]);
            acc[2][1] = fmaf(a2, bb.y, acc[2][1]);
            acc[2][2] = fmaf(a2, bb.z, acc[2][2]);
            acc[2][3] = fmaf(a2, bb.w, acc[2][3]);
            acc[3][0] = fmaf(a3, bb.x, acc[3][0]);
            acc[3][1] = fmaf(a3, bb.y, acc[3][1]);
            acc[3][2] = fmaf(a3, bb.z, acc[3][2]);
            acc[3][3] = fmaf(a3, bb.w, acc[3][3]);
        }
    }

    #pragma unroll
    for (int ii = 0; ii < 4; ++ii) {
        int m = m0 + ty * 4 + ii;
        #pragma unroll
        for (int jj = 0; jj < 4; ++jj) {
            int n = n0 + tx * 4 + jj;
            if (n < N) {
                float v = acc[ii][jj] + bias[n];
                if (RELU) v = fmaxf(v, 0.f);
                C[(size_t)m * N + n] = v;
            }
        }
    }
}

// ---------------------------------------------------------------------------
// QP solver. One CTA (256 thr) per batch item.
//   rH[32]: thread t holds H[r][32h+k],  r=t>>1, h=t&1    (row-matvec phase)
//   rM[16]: thread t holds Minv[c][16g+j], c=t>>2, g=t&3  (inverse rows)
//   H^T matvecs read columns from dyn-smem sH (stride 65, g-rotated banks).
// ---------------------------------------------------------------------------
__device__ __forceinline__ float sel16(const float* r, int kj) {
    float v = r[0];
    #pragma unroll
    for (int j = 1; j < 16; ++j) v = (j == kj) ? r[j] : v;
    return v;
}

#define SOLVER_SMEM_FLOATS (128 * 65 + 64 * 65)

__global__ __launch_bounds__(256, 2)
void solver_kernel(const float* __restrict__ out3, float* __restrict__ xs)
{
    extern __shared__ __align__(16) float smdyn[];
    float* sH = smdyn;              // 128*65  (H, persistent)
    float* sQ = sH + 128 * 65;      // 64*65   (L, then dead)

    __shared__ __align__(16) float spiv[2 * 64];
    __shared__ __align__(16) float sxbar[64];
    __shared__ __align__(16) float st[64];
    __shared__ __align__(16) float slam[128];
    __shared__ __align__(16) float sb[128];
    __shared__ __align__(16) float sq[64];
    __shared__ __align__(16) float sv[64];
    __shared__ __align__(16) float sw[128];
    __shared__ float spart[8];
    __shared__ float s_scal, s_tau;

    const int t    = threadIdx.x;
    const int lane = t & 31;
    const int warp = t >> 5;
    const int r    = t >> 1;   // 0..127
    const int h    = t & 1;
    const int c    = t >> 2;   // 0..63
    const int g    = t & 3;

    const float* row = out3 + (size_t)blockIdx.x * N_OUT;
    const unsigned FULL = 0xffffffffu;

    // ---- Load H into registers (coalesced) and smem ----
    float rH[32];
    {
        const float4* base = (const float4*)(row + HOFF + r * 64 + 32 * h);
        #pragma unroll
        for (int k4 = 0; k4 < 8; ++k4) {
            float4 v = base[k4];
            rH[4*k4+0] = v.x; rH[4*k4+1] = v.y; rH[4*k4+2] = v.z; rH[4*k4+3] = v.w;
            sH[r * 65 + 32 * h + 4 * k4 + 0] = v.x;
            sH[r * 65 + 32 * h + 4 * k4 + 1] = v.y;
            sH[r * 65 + 32 * h + 4 * k4 + 2] = v.z;
            sH[r * 65 + 32 * h + 4 * k4 + 3] = v.w;
        }
    }
    if (t < 64)  sq[t] = row[N_P + t];
    if (t < 128) sb[t] = row[HOFF + N_HMAT + t];
    if (t < 64)  sv[t] = 0.125f;
    __syncthreads();

    // ================= Power iteration =================
    for (int pit = 0; pit < 10; ++pit) {
        // w = H v  (threads r,h; 4 accumulators)
        {
            const float4* x4 = (const float4*)(sv + 32 * h);
            float a0=0.f,a1=0.f,a2=0.f,a3=0.f;
            #pragma unroll
            for (int k4 = 0; k4 < 8; ++k4) {
                float4 xv = x4[k4];
                a0 = fmaf(rH[4*k4+0], xv.x, a0);
                a1 = fmaf(rH[4*k4+1], xv.y, a1);
                a2 = fmaf(rH[4*k4+2], xv.z, a2);
                a3 = fmaf(rH[4*k4+3], xv.w, a3);
            }
            float s = (a0 + a1) + (a2 + a3);
            s += __shfl_xor_sync(FULL, s, 1);
            if (h == 0) sw[r] = s;
        }
        __syncthreads();
        // p = (H^T w)[c] (threads c,g; smem column reads, bank-rotated)
        {
            float a0=0.f,a1=0.f,a2=0.f,a3=0.f;
            #pragma unroll
            for (int j0 = 0; j0 < 32; j0 += 4) {
                int jj0 = (j0 + 0 + 8 * g) & 31;
                int jj1 = (j0 + 1 + 8 * g) & 31;
                int jj2 = (j0 + 2 + 8 * g) & 31;
                int jj3 = (j0 + 3 + 8 * g) & 31;
                a0 = fmaf(sH[(32*g + jj0) * 65 + c], sw[32*g + jj0], a0);
                a1 = fmaf(sH[(32*g + jj1) * 65 + c], sw[32*g + jj1], a1);
                a2 = fmaf(sH[(32*g + jj2) * 65 + c], sw[32*g + jj2], a2);
                a3 = fmaf(sH[(32*g + jj3) * 65 + c], sw[32*g + jj3], a3);
            }
            float p = (a0 + a1) + (a2 + a3);
            p += __shfl_xor_sync(FULL, p, 1);
            p += __shfl_xor_sync(FULL, p, 2);
            float pp = (g == 0) ? p * p : 0.f;
            #pragma unroll
            for (int off = 16; off >= 1; off >>= 1)
                pp += __shfl_xor_sync(FULL, pp, off);
            if (lane == 0) spart[warp] = pp;
            __syncthreads();
            if (t == 0) {
                float sm = 0.f;
                #pragma unroll
                for (int i = 0; i < 8; ++i) sm += spart[i];
                s_scal = sqrtf(sm) + 1e-12f;
            }
            __syncthreads();
            if (g == 0) sv[c] = p / s_scal;
        }
        __syncthreads();
    }

    // ---- tau = 0.9/(||H v|| + 1e-6) ----
    {
        const float4* x4 = (const float4*)(sv + 32 * h);
        float a0=0.f,a1=0.f,a2=0.f,a3=0.f;
        #pragma unroll
        for (int k4 = 0; k4 < 8; ++k4) {
            float4 xv = x4[k4];
            a0 = fmaf(rH[4*k4+0], xv.x, a0);
            a1 = fmaf(rH[4*k4+1], xv.y, a1);
            a2 = fmaf(rH[4*k4+2], xv.z, a2);
            a3 = fmaf(rH[4*k4+3], xv.w, a3);
        }
        float s = (a0 + a1) + (a2 + a3);
        s += __shfl_xor_sync(FULL, s, 1);
        float pp = (h == 0) ? s * s : 0.f;
        #pragma unroll
        for (int off = 16; off >= 1; off >>= 1)
            pp += __shfl_xor_sync(FULL, pp, off);
        if (lane == 0) spart[warp] = pp;
        __syncthreads();
        if (t == 0) {
            float sm = 0.f;
            #pragma unroll
            for (int i = 0; i < 8; ++i) sm += spart[i];
            s_tau = 0.9f / (sqrtf(sm) + 1e-6f);
        }
    }

    // ================= Build L =================
    for (int idx = t; idx < 64 * 65; idx += 256) sQ[idx] = 0.f;
    __syncthreads();
    for (int idx = t; idx < N_P; idx += 256) {
        float p = row[idx];
        int rr = (int)((sqrtf(8.f * (float)idx + 1.f) - 1.f) * 0.5f);
        while ((rr * (rr + 1)) / 2 > idx) --rr;
        while (((rr + 1) * (rr + 2)) / 2 <= idx) ++rr;
        int cc = idx - (rr * (rr + 1)) / 2;
        float val;
        if (cc == rr) {
            float sp = fmaxf(p, 0.f) + log1pf(expf(-fabsf(p)));
            val = 0.1f + sp;
        } else {
            val = p;
        }
        sQ[rr * 65 + cc] = val;
    }
    __syncthreads();
    const float tau = s_tau;
    const float sig = tau;

    // ================= rM = I + tau * (L L^T) slice  (thread c,g) ==========
    float rM[16];
    #pragma unroll
    for (int j = 0; j < 16; ++j) rM[j] = 0.f;
    for (int k = 0; k < 64; ++k) {
        float a = sQ[c * 65 + k];
        #pragma unroll
        for (int j = 0; j < 16; ++j)
            rM[j] = fmaf(a, sQ[(16 * g + j) * 65 + k], rM[j]);
    }
    #pragma unroll
    for (int j = 0; j < 16; ++j) {
        int col = 16 * g + j;
        rM[j] = tau * rM[j] + ((col == c) ? 1.f : 0.f);
    }
    __syncthreads();   // everyone done reading sQ (it's dead now)

    // ================= Gauss-Jordan inverse (1 barrier / pivot) ============
    // praw = M[own_row][k] via ONE unconditional shuffle:
    //   pivot row (c==k): praw = pivot value
    //   other rows:       praw = elimination factor f
    for (int k = 0; k < 64; ++k) {
        const int kc = k >> 4, kj = k & 15;
        float* buf = spiv + (k & 1) * 64;
        float praw = __shfl_sync(FULL, sel16(rM, kj), (lane & ~3) | kc);
        if (c == k) {
            float pinv = 1.f / praw;
            #pragma unroll
            for (int j = 0; j < 16; ++j) {
                bool isk = (g == kc) && (j == kj);
                rM[j] = isk ? pinv : rM[j] * pinv;
            }
            *(float4*)&buf[16*g +  0] = make_float4(rM[0],  rM[1],  rM[2],  rM[3]);
            *(float4*)&buf[16*g +  4] = make_float4(rM[4],  rM[5],  rM[6],  rM[7]);
            *(float4*)&buf[16*g +  8] = make_float4(rM[8],  rM[9],  rM[10], rM[11]);
            *(float4*)&buf[16*g + 12] = make_float4(rM[12], rM[13], rM[14], rM[15]);
        }
        __syncthreads();
        if (c != k) {
            const float f = praw;
            float4 p0 = *(const float4*)&buf[16*g +  0];
            float4 p1 = *(const float4*)&buf[16*g +  4];
            float4 p2 = *(const float4*)&buf[16*g +  8];
            float4 p3 = *(const float4*)&buf[16*g + 12];
            float pv[16] = {p0.x,p0.y,p0.z,p0.w, p1.x,p1.y,p1.z,p1.w,
                            p2.x,p2.y,p2.z,p2.w, p3.x,p3.y,p3.z,p3.w};
            #pragma unroll
            for (int j = 0; j < 16; ++j) {
                bool isk = (g == kc) && (j == kj);
                float upd = fmaf(-f, pv[j], rM[j]);
                rM[j] = isk ? (-f * pv[j]) : upd;   // pv[kj] == 1/piv
            }
        }
    }
    __syncthreads();

    // ================= QP iterations =================
    if (t < 64)  { sxbar[t] = 0.f; st[t] = 0.f; }
    if (t < 128) slam[t] = 0.f;
    float xp = 0.f;
    __syncthreads();

    for (int it = 0; it < QP_ITER; ++it) {
        // lam = relu(lam - sig*(H xbar + b))   (threads r,h)
        {
            const float4* x4 = (const float4*)(sxbar + 32 * h);
            float a0=0.f,a1=0.f,a2=0.f,a3=0.f;
            #pragma unroll
            for (int k4 = 0; k4 < 8; ++k4) {
                float4 xv = x4[k4];
                a0 = fmaf(rH[4*k4+0], xv.x, a0);
                a1 = fmaf(rH[4*k4+1], xv.y, a1);
                a2 = fmaf(rH[4*k4+2], xv.z, a2);
                a3 = fmaf(rH[4*k4+3], xv.w, a3);
            }
            float s = (a0 + a1) + (a2 + a3);
            s += __shfl_xor_sync(FULL, s, 1);
            if (h == 0) slam[r] = fmaxf(0.f, slam[r] - sig * (s + sb[r]));
        }
        __syncthreads();
        // t = xp + tau*(H^T lam - q)   (threads c,g; smem columns)
        {
            float a0=0.f,a1=0.f,a2=0.f,a3=0.f;
            #pragma unroll
            for (int j0 = 0; j0 < 32; j0 += 4) {
                int jj0 = (j0 + 0 + 8 * g) & 31;
                int jj1 = (j0 + 1 + 8 * g) & 31;
                int jj2 = (j0 + 2 + 8 * g) & 31;
                int jj3 = (j0 + 3 + 8 * g) & 31;
                a0 = fmaf(sH[(32*g + jj0) * 65 + c], slam[32*g + jj0], a0);
                a1 = fmaf(sH[(32*g + jj1) * 65 + c], slam[32*g + jj1], a1);
                a2 = fmaf(sH[(32*g + jj2) * 65 + c], slam[32*g + jj2], a2);
                a3 = fmaf(sH[(32*g + jj3) * 65 + c], slam[32*g + jj3], a3);
            }
            float p = (a0 + a1) + (a2 + a3);
            p += __shfl_xor_sync(FULL, p, 1);
            p += __shfl_xor_sync(FULL, p, 2);
            if (g == 0) st[c] = xp + tau * (p - sq[c]);
        }
        __syncthreads();
        // xn = Minv t ; xbar = 2 xn - xp ; xp = xn   (threads c,g)
        {
            const float4* t4 = (const float4*)(st + 16 * g);
            float4 t0 = t4[0], t1 = t4[1], t2 = t4[2], t3 = t4[3];
            float a0=0.f,a1=0.f,a2=0.f,a3=0.f;
            a0 = fmaf(rM[0],  t0.x, a0); a1 = fmaf(rM[1],  t0.y, a1);
            a2 = fmaf(rM[2],  t0.z, a2); a3 = fmaf(rM[3],  t0.w, a3);
            a0 = fmaf(rM[4],  t1.x, a0); a1 = fmaf(rM[5],  t1.y, a1);
            a2 = fmaf(rM[6],  t1.z, a2); a3 = fmaf(rM[7],  t1.w, a3);
            a0 = fmaf(rM[8],  t2.x, a0); a1 = fmaf(rM[9],  t2.y, a1);
            a2 = fmaf(rM[10], t2.z, a2); a3 = fmaf(rM[11], t2.w, a3);
            a0 = fmaf(rM[12], t3.x, a0); a1 = fmaf(rM[13], t3.y, a1);
            a2 = fmaf(rM[14], t3.z, a2); a3 = fmaf(rM[15], t3.w, a3);
            float p = (a0 + a1) + (a2 + a3);
            p += __shfl_xor_sync(FULL, p, 1);
            p += __shfl_xor_sync(FULL, p, 2);
            if (g == 0) {
                sxbar[c] = 2.f * p - xp;
                xp = p;
            }
        }
        __syncthreads();
    }

    if (g == 0) xs[(size_t)blockIdx.x * N_QP + c] = xp;
}

// ---------------------------------------------------------------------------
// Launch
// ---------------------------------------------------------------------------
extern "C" void kernel_launch(void* const* d_in, const int* in_sizes, int n_in,
                              void* d_out, int out_size)
{
    const float* x  = (const float*)d_in[0];
    const float* W1 = (const float*)d_in[1];
    const float* b1 = (const float*)d_in[2];
    const float* W2 = (const float*)d_in[3];
    const float* b2 = (const float*)d_in[4];
    const float* W3 = (const float*)d_in[5];
    const float* b3 = (const float*)d_in[6];
    float* out = (float*)d_out;

    float *p_h1, *p_h2, *p_out3;
    cudaGetSymbolAddress((void**)&p_h1, g_h1);
    cudaGetSymbolAddress((void**)&p_h2, g_h2);
    cudaGetSymbolAddress((void**)&p_out3, g_out3);

    {
        dim3 grid(HIDDEN / 64, BATCH / 64);
        sgemm_bias<true><<<grid, 256>>>(x, W1, b1, p_h1, BATCH, HIDDEN, INPUT_SIZE);
    }
    {
        dim3 grid(HIDDEN / 64, BATCH / 64);
        sgemm_bias<true><<<grid, 256>>>(p_h1, W2, b2, p_h2, BATCH, HIDDEN, HIDDEN);
    }
    {
        dim3 grid((N_OUT + 63) / 64, BATCH / 64);
        sgemm_bias<false><<<grid, 256>>>(p_h2, W3, b3, p_out3, BATCH, N_OUT, HIDDEN);
    }
    {
        const size_t smem_bytes = (size_t)SOLVER_SMEM_FLOATS * sizeof(float);
        cudaFuncSetAttribute(solver_kernel,
                             cudaFuncAttributeMaxDynamicSharedMemorySize,
                             (int)smem_bytes);
        solver_kernel<<<BATCH, 256, smem_bytes>>>(p_out3, out);
    }
}